// round 14
// baseline (speedup 1.0000x reference)
#include <cuda_runtime.h>
#include <math.h>
#include <stdint.h>

#define B_   512
#define NW   64
#define NQ   343
#define NTOK 344
#define DIM  96
#define H    3
#define HD   32
#define NROWS (B_*NTOK)
#define XOUT_SZ ((size_t)B_*NQ*DIM)
#define BMSTR 344
#define RLN2  1.4426950408889634f

typedef unsigned long long u64;

__device__ float g_att[(size_t)B_*NTOK*DIM];
__device__ float g_bm[(size_t)H*NW*NQ*BMSTR + 16];

// ---------------- kernel 0: bm gather, x4, pre-scaled by log2(e) ----------
__global__ void bm_pre_kernel(const float* __restrict__ btab,
                              const int* __restrict__ ri,
                              const float* __restrict__ mask) {
    size_t gid = (size_t)blockIdx.x * 256 + threadIdx.x;
    if (gid >= (size_t)H*NW*NQ*86) return;
    int q  = (int)(gid % 86);
    size_t t = gid / 86;
    int r  = (int)(t % NQ);
    int hw = (int)(t / NQ);
    int h = hw / NW, w = hw % NW;
    int j0 = q*4;
    const int*   rr = ri + (size_t)r*NQ;
    const float* mr = mask + (size_t)w*NQ*NQ + (size_t)r*NQ;
    float v[4];
    #pragma unroll
    for (int e = 0; e < 4; ++e) {
        int j = j0 + e;
        v[e] = 0.f;
        if (j >= 1)
            v[e] = (btab[rr[j-1]*H + h] + mr[j-1]) * RLN2;
    }
    *(float4*)&g_bm[((size_t)hw*NQ + r)*BMSTR + j0] =
        make_float4(v[0], v[1], v[2], v[3]);
}

// ---------------- helpers ----------------
__device__ __forceinline__ u64 pk2(float lo, float hi) {
    u64 r; asm("mov.b64 %0, {%1, %2};" : "=l"(r) : "f"(lo), "f"(hi)); return r;
}
__device__ __forceinline__ void upk2(float& lo, float& hi, u64 v) {
    asm("mov.b64 {%0, %1}, %2;" : "=f"(lo), "=f"(hi) : "l"(v));
}
__device__ __forceinline__ void fma2(u64& d, u64 a, u64 b) {
    asm("fma.rn.f32x2 %0, %1, %2, %3;" : "=l"(d) : "l"(a), "l"(b), "l"(d));
}
__device__ __forceinline__ float ex2f(float x) {
    float r; asm("ex2.approx.f32 %0, %1;" : "=f"(r) : "f"(x)); return r;
}

// fused smem layout (bytes):
//  phase1 (aliased, dead after epilogue):
//    Xs f32[352][98] @0 (137984) | Wf u64[96][48] @137984 (36864, ends 174848)
//  phase2: P u64/warp @wid*2112 [0,46464) | Qs @56960 | Kt @104832 | Vs @150400
//  bis f32[96] @201088 (never aliased)
#define SM_QS   56960
#define SM_KT   104832
#define SM_VS   150400
#define SM_WF   137984
#define SM_BIS  201088
#define FUSED_SMEM 201472

__global__ void __launch_bounds__(704, 1)
fused_attn_kernel(const float* __restrict__ x,
                  const float* __restrict__ gt,
                  const float* __restrict__ Wqkv,
                  const float* __restrict__ bqkv) {
    extern __shared__ char smem[];
    float* Xs  = (float*)smem;                 // [352][98]
    u64*   Wf  = (u64*)(smem + SM_WF);         // [96][48]
    float* bis = (float*)(smem + SM_BIS);      // [96]
    float* Qs  = (float*)(smem + SM_QS);       // [176 pairs][68]
    float* Kt  = (float*)(smem + SM_KT);       // [32][356]
    float* Vs  = (float*)(smem + SM_VS);       // [352][36]

    const int bid = blockIdx.x;
    const int rep = bid & 7;
    const int hw  = bid >> 3;
    const int w   = hw & 63;
    const int h   = hw >> 6;
    const int b   = (rep << 6) + w;

    const int tid  = threadIdx.x;
    const int wid  = tid >> 5;
    const int lane = tid & 31;
    const int rg   = lane >> 3;     // 4 row-groups of 4 rows
    const int cg   = lane & 7;      // 8 col-groups of 6 colpairs
    const float scale = 0.17677669529663687f * RLN2;
    const int mb = wid * 16;

    // ---- fills: X fp32, W colpairs, bias ----
    for (int idx = tid; idx < 352*48; idx += 704) {
        int n = idx / 48, c2 = idx % 48;
        float2 v2 = make_float2(0.f, 0.f);
        if (n < NTOK) {
            const float* src = (n == 0) ? (gt + (size_t)b*DIM)
                                        : (x + ((size_t)b*NQ + (n-1))*DIM);
            v2 = *(const float2*)(src + 2*c2);
        }
        *(float2*)&Xs[n*98 + 2*c2] = v2;
    }
    for (int idx = tid; idx < 96*48; idx += 704) {
        int k = idx / 48, cp = idx % 48;
        int ce = 2*cp, co = ce + 1;
        int re = (ce < 32) ? (h*HD + ce)
               : (ce < 64) ? (DIM + h*HD + (ce-32))
                           : (2*DIM + h*HD + (ce-64));
        int ro = (co < 32) ? (h*HD + co)
               : (co < 64) ? (DIM + h*HD + (co-32))
                           : (2*DIM + h*HD + (co-64));
        Wf[idx] = pk2(Wqkv[(size_t)re*DIM + k], Wqkv[(size_t)ro*DIM + k]);
    }
    if (tid < 96) {
        int c = tid;
        int row = (c < 32) ? (h*HD + c)
                : (c < 64) ? (DIM + h*HD + (c-32))
                           : (2*DIM + h*HD + (c-64));
        bis[c] = bqkv[row];
    }
    __syncthreads();

    // ---- phase 1: f32x2 GEMM, spill-safe (w consumed immediately) ----
    u64 a2[24];
    #pragma unroll
    for (int i = 0; i < 24; ++i) a2[i] = pk2(0.f, 0.f);

    {
        const float* xrow = Xs + (mb + rg*4)*98;
        const u64*   wrow = Wf + cg*6;
        #pragma unroll 2
        for (int k = 0; k < 96; ++k) {
            float x0 = xrow[k];
            float x1 = xrow[98 + k];
            float x2v = xrow[196 + k];
            float x3 = xrow[294 + k];
            u64 s0 = pk2(x0, x0);
            u64 s1 = pk2(x1, x1);
            u64 s2 = pk2(x2v, x2v);
            u64 s3 = pk2(x3, x3);
            const u64* wk = wrow + (size_t)k*48;
            #pragma unroll
            for (int j = 0; j < 6; ++j) {
                u64 wv = wk[j];
                fma2(a2[j],      s0, wv);
                fma2(a2[6 + j],  s1, wv);
                fma2(a2[12 + j], s2, wv);
                fma2(a2[18 + j], s3, wv);
            }
        }
    }
    __syncthreads();   // phase-1 reads done before epilogue overwrites aliases

    // ---- epilogue: scatter to Qs / Kt / Vs ----
    #pragma unroll
    for (int i = 0; i < 4; ++i) {
        int n = mb + rg*4 + i;
        #pragma unroll
        for (int j = 0; j < 6; ++j) {
            float ve, vo;
            upk2(ve, vo, a2[i*6 + j]);
            int ce = (cg*6 + j)*2;
            ve += bis[ce];
            vo += bis[ce+1];
            int sec = ce >> 5, d = ce & 31;
            if (sec == 0) {
                Qs[(n>>1)*68 + d*2     + (n&1)] = ve*scale;
                Qs[(n>>1)*68 + (d+1)*2 + (n&1)] = vo*scale;
            } else if (sec == 1) {
                Kt[d*356 + n]     = ve;
                Kt[(d+1)*356 + n] = vo;
            } else {
                Vs[n*36 + d]     = ve;
                Vs[n*36 + d + 1] = vo;
            }
        }
    }
    __syncthreads();

    // ---- phase 2: f32x2 attention (R13 proven) ----
    const int tq = lane >> 3;
    const int tk = lane & 7;
    u64* Pw = (u64*)(smem + wid*2112);
    const float* bmb = g_bm + ((size_t)(h*NW + w)) * NQ * BMSTR;
    const int q0 = mb + tq*4;
    const int pr0 = tq*2;

    u64 o2[2][4];
    float l4[4] = {0.f, 0.f, 0.f, 0.f};
    #pragma unroll
    for (int p = 0; p < 2; ++p)
        #pragma unroll
        for (int c = 0; c < 4; ++c) o2[p][c] = pk2(0.f, 0.f);

    for (int kb = 0; kb < 11; ++kb) {
        const int kbase = kb*32;

        float4 bmv[2][2];
        #pragma unroll
        for (int p = 0; p < 2; ++p) {
            int re = q0 + 2*p, ro = re + 1;
            bool ve = (re >= 1) && (re < NTOK);
            bool vo = (ro < NTOK);
            bmv[p][0] = ve ? __ldg((const float4*)(bmb + (size_t)(re-1)*BMSTR + kbase + tk*4))
                           : make_float4(0.f,0.f,0.f,0.f);
            bmv[p][1] = vo ? __ldg((const float4*)(bmb + (size_t)(ro-1)*BMSTR + kbase + tk*4))
                           : make_float4(0.f,0.f,0.f,0.f);
        }

        u64 acc2[2][4];
        #pragma unroll
        for (int p = 0; p < 2; ++p)
            #pragma unroll
            for (int c = 0; c < 4; ++c) acc2[p][c] = pk2(0.f, 0.f);

        const float* kp = Kt + kbase + tk*4;
        const float* qp = Qs + (q0>>1)*68;
        #pragma unroll 8
        for (int d = 0; d < 32; ++d) {
            u64 qa = *(const u64*)(qp + 2*d);
            u64 qb = *(const u64*)(qp + 68 + 2*d);
            float4 kv = *(const float4*)(kp + d*356);
            u64 k20 = pk2(kv.x, kv.x), k21 = pk2(kv.y, kv.y);
            u64 k22 = pk2(kv.z, kv.z), k23 = pk2(kv.w, kv.w);
            fma2(acc2[0][0], qa, k20); fma2(acc2[0][1], qa, k21);
            fma2(acc2[0][2], qa, k22); fma2(acc2[0][3], qa, k23);
            fma2(acc2[1][0], qb, k20); fma2(acc2[1][1], qb, k21);
            fma2(acc2[1][2], qb, k22); fma2(acc2[1][3], qb, k23);
        }

        #pragma unroll
        for (int p = 0; p < 2; ++p) {
            float be[4] = {bmv[p][0].x, bmv[p][0].y, bmv[p][0].z, bmv[p][0].w};
            float bo[4] = {bmv[p][1].x, bmv[p][1].y, bmv[p][1].z, bmv[p][1].w};
            #pragma unroll
            for (int c = 0; c < 4; ++c) {
                float se, so;
                upk2(se, so, acc2[p][c]);
                int j = kbase + tk*4 + c;
                float pe = (j < NTOK) ? ex2f(se + be[c]) : 0.f;
                float po = (j < NTOK) ? ex2f(so + bo[c]) : 0.f;
                l4[2*p]   += pe;
                l4[2*p+1] += po;
                Pw[(pr0 + p)*33 + tk*4 + c] = pk2(pe, po);
            }
        }
        __syncwarp();

        const float* vp = Vs + (size_t)kbase*36 + tk*4;
        #pragma unroll 8
        for (int j = 0; j < 32; ++j) {
            u64 p20 = Pw[pr0*33 + j];
            u64 p21 = Pw[(pr0+1)*33 + j];
            float4 vv = *(const float4*)(vp + j*36);
            u64 v20 = pk2(vv.x, vv.x), v21 = pk2(vv.y, vv.y);
            u64 v22 = pk2(vv.z, vv.z), v23 = pk2(vv.w, vv.w);
            fma2(o2[0][0], p20, v20); fma2(o2[0][1], p20, v21);
            fma2(o2[0][2], p20, v22); fma2(o2[0][3], p20, v23);
            fma2(o2[1][0], p21, v20); fma2(o2[1][1], p21, v21);
            fma2(o2[1][2], p21, v22); fma2(o2[1][3], p21, v23);
        }
        __syncwarp();
    }

    #pragma unroll
    for (int a = 0; a < 4; ++a) {
        l4[a] += __shfl_xor_sync(0xffffffffu, l4[a], 1);
        l4[a] += __shfl_xor_sync(0xffffffffu, l4[a], 2);
        l4[a] += __shfl_xor_sync(0xffffffffu, l4[a], 4);
    }
    #pragma unroll
    for (int p = 0; p < 2; ++p) {
        float oe[4], oo[4];
        #pragma unroll
        for (int c = 0; c < 4; ++c) upk2(oe[c], oo[c], o2[p][c]);
        int re = q0 + 2*p, ro = re + 1;
        if (re < NTOK) {
            float inv = 1.f / l4[2*p];
            *(float4*)(g_att + ((size_t)b*NTOK + re)*DIM + h*HD + tk*4) =
                make_float4(oe[0]*inv, oe[1]*inv, oe[2]*inv, oe[3]*inv);
        }
        if (ro < NTOK) {
            float inv = 1.f / l4[2*p+1];
            *(float4*)(g_att + ((size_t)b*NTOK + ro)*DIM + h*HD + tk*4) =
                make_float4(oo[0]*inv, oo[1]*inv, oo[2]*inv, oo[3]*inv);
        }
    }
}

// ---------------- proj: R12 proven f32x2 version (unchanged) ----------------
#define PROJ_SMEM (25088 + 38784)
__global__ void __launch_bounds__(256, 3)
proj_kernel(const float* __restrict__ W,
            const float* __restrict__ bp,
            float* __restrict__ dout) {
    extern __shared__ char psm[];
    float* Ai  = (float*)psm;               // [32][196]
    float* Wsm = (float*)(psm + 25088);     // [96][101]
    const int tid  = threadIdx.x;
    const int row0 = blockIdx.x * 64;
    const int rg = tid >> 5;
    const int cg = tid & 31;

    for (int idx = tid; idx < 32*24; idx += 256) {
        int rp = idx / 24, kq = idx % 24;
        float4 e = *(const float4*)(g_att + (size_t)(row0 + 2*rp)*DIM + 4*kq);
        float4 o = *(const float4*)(g_att + (size_t)(row0 + 2*rp + 1)*DIM + 4*kq);
        *(float4*)&Ai[rp*196 + 8*kq]     = make_float4(e.x, o.x, e.y, o.y);
        *(float4*)&Ai[rp*196 + 8*kq + 4] = make_float4(e.z, o.z, e.w, o.w);
    }
    for (int idx = tid; idx < 96*24; idx += 256) {
        int c = idx / 24, kq = idx % 24;
        float4 wv = *(const float4*)(W + (size_t)c*DIM + 4*kq);
        Wsm[c*101 + 4*kq]     = wv.x;
        Wsm[c*101 + 4*kq + 1] = wv.y;
        Wsm[c*101 + 4*kq + 2] = wv.z;
        Wsm[c*101 + 4*kq + 3] = wv.w;
    }
    __syncthreads();

    u64 a2[4][3];
    #pragma unroll
    for (int i = 0; i < 4; ++i)
        #pragma unroll
        for (int j = 0; j < 3; ++j) a2[i][j] = pk2(0.f, 0.f);

    const float* arow = Ai + rg*4*196;
    const float* wrow = Wsm + cg*3*101;
    #pragma unroll 4
    for (int k = 0; k < 96; ++k) {
        u64 x2[4];
        #pragma unroll
        for (int i = 0; i < 4; ++i)
            x2[i] = *(const u64*)(arow + i*196 + 2*k);
        u64 w0 = pk2(wrow[k],       wrow[k]);
        u64 w1 = pk2(wrow[101 + k], wrow[101 + k]);
        u64 w2 = pk2(wrow[202 + k], wrow[202 + k]);
        #pragma unroll
        for (int i = 0; i < 4; ++i) {
            fma2(a2[i][0], x2[i], w0);
            fma2(a2[i][1], x2[i], w1);
            fma2(a2[i][2], x2[i], w2);
        }
    }

    #pragma unroll
    for (int i = 0; i < 4; ++i) {
        #pragma unroll
        for (int j = 0; j < 3; ++j) {
            float ve, vo;
            upk2(ve, vo, a2[i][j]);
            int c = cg*3 + j;
            float bb = __ldg(bp + c);
            ve += bb; vo += bb;
            int gre = row0 + (rg*4 + i)*2;
            int gro = gre + 1;
            int be_ = gre / NTOK, ne = gre % NTOK;
            int bo_ = gro / NTOK, no = gro % NTOK;
            if (ne == 0) dout[XOUT_SZ + (size_t)be_*DIM + c] = ve;
            else         dout[((size_t)be_*NQ + (ne-1))*DIM + c] = ve;
            if (no == 0) dout[XOUT_SZ + (size_t)bo_*DIM + c] = vo;
            else         dout[((size_t)bo_*NQ + (no-1))*DIM + c] = vo;
        }
    }
}

// ---------------- launch ----------------
extern "C" void kernel_launch(void* const* d_in, const int* in_sizes, int n_in,
                              void* d_out, int out_size) {
    const float* x     = (const float*)d_in[0];
    const float* gt    = (const float*)d_in[1];
    const float* mask  = (const float*)d_in[2];
    const int*   ri    = (const int*)  d_in[3];
    const float* Wqkv  = (const float*)d_in[4];
    const float* bqkv  = (const float*)d_in[5];
    const float* Wproj = (const float*)d_in[6];
    const float* bproj = (const float*)d_in[7];
    const float* btab  = (const float*)d_in[8];
    float* out = (float*)d_out;

    cudaFuncSetAttribute(fused_attn_kernel, cudaFuncAttributeMaxDynamicSharedMemorySize, FUSED_SMEM);
    cudaFuncSetAttribute(proj_kernel,       cudaFuncAttributeMaxDynamicSharedMemorySize, PROJ_SMEM);

    {
        size_t total = (size_t)H*NW*NQ*86;
        bm_pre_kernel<<<(unsigned)((total + 255)/256), 256>>>(btab, ri, mask);
    }
    fused_attn_kernel<<<B_*H, 704, FUSED_SMEM>>>(x, gt, Wqkv, bqkv);
    proj_kernel<<<NROWS/64, 256, PROJ_SMEM>>>(Wproj, bproj, out);
}